// round 1
// baseline (speedup 1.0000x reference)
#include <cuda_runtime.h>
#include <stdint.h>

#define NNODES 50000
#define NEDGES 600000

// ---------------- scratch (static device globals; no dynamic alloc) ----------
__device__ float g_x0[(size_t)NNODES * 128];
__device__ float g_x1[(size_t)NNODES * 128];
__device__ float g_x2[(size_t)NNODES * 128];
__device__ float g_x3[(size_t)NNODES * 128];
__device__ float g_xa[(size_t)NNODES * 384];
__device__ float g_wcat[384 * 128];
__device__ int   g_cnt[NNODES];
__device__ int   g_rowptr[NNODES + 1];
__device__ int   g_cursor[NNODES];
__device__ int   g_adj[NEDGES];

// ---------------- helpers ----------------------------------------------------
typedef unsigned long long ull;

__device__ __forceinline__ float lrelu(float x) { return x > 0.f ? x : 0.01f * x; }

__device__ __forceinline__ void ffma2(ull& d, ull a, ull b, ull c) {
    asm("fma.rn.f32x2 %0, %1, %2, %3;" : "=l"(d) : "l"(a), "l"(b), "l"(c));
}
__device__ __forceinline__ ull dup2(float x) {
    ull r; asm("mov.b64 %0, {%1, %1};" : "=l"(r) : "f"(x)); return r;
}
__device__ __forceinline__ float2 unpk(ull v) {
    float2 r; asm("mov.b64 {%0, %1}, %2;" : "=f"(r.x), "=f"(r.y) : "l"(v)); return r;
}

// ---------------- generic fused GEMM: C = act(A[M,K] @ W[K,NC] + b) ----------
// BM=128 rows/block, BN cols/block, BK=16, 256 threads.
// Accumulators packed as f32x2 over row pairs -> FFMA2 inner loop.
template <int BN>
__global__ __launch_bounds__(256) void gemm_kernel(
    const float* __restrict__ A, int lda,
    const float* __restrict__ W, int ldw,
    const float* __restrict__ bias,
    float* __restrict__ C, int ldc, int col_off,
    int M, int K, int NC, int relu)
{
    constexpr int BM = 128, BK = 16;
    constexpr int NTX = BN / 4;         // threads along cols (each does 4 cols)
    constexpr int NTY = 256 / NTX;      // threads along rows
    constexpr int TM  = BM / NTY;       // rows per thread (even)
    constexpr int NPAIR = TM / 2;

    __shared__ float As[BK][BM];
    __shared__ float Bs[BK][BN];

    const int tid = threadIdx.x;
    const int tx = tid % NTX, ty = tid / NTX;
    const int bm = blockIdx.x * BM;
    const int bn = blockIdx.y * BN;

    ull acc[NPAIR][4];
#pragma unroll
    for (int p = 0; p < NPAIR; p++)
#pragma unroll
        for (int j = 0; j < 4; j++) acc[p][j] = 0ull;

    for (int k0 = 0; k0 < K; k0 += BK) {
        // A tile (transposed into As[k][m]); K is always a multiple of 16 here.
#pragma unroll
        for (int i = 0; i < 2; i++) {
            int idx = tid * 2 + i;           // 0..511
            int row = idx >> 2;
            int kq = (idx & 3) << 2;
            float4 v = make_float4(0.f, 0.f, 0.f, 0.f);
            int gr = bm + row;
            if (gr < M)
                v = *reinterpret_cast<const float4*>(A + (size_t)gr * lda + k0 + kq);
            As[kq + 0][row] = v.x;
            As[kq + 1][row] = v.y;
            As[kq + 2][row] = v.z;
            As[kq + 3][row] = v.w;
        }
        // B tile
        constexpr int EB = (BK * BN) / 256;
#pragma unroll
        for (int i = 0; i < EB; i++) {
            int idx = tid * EB + i;
            int krow = idx / BN;
            int col = idx % BN;
            int gc = bn + col;
            float v = 0.f;
            if (gc < NC) v = W[(size_t)(k0 + krow) * ldw + gc];
            Bs[krow][col] = v;
        }
        __syncthreads();

#pragma unroll
        for (int kk = 0; kk < BK; kk++) {
            const float* ap = &As[kk][ty * TM];
            ull a[NPAIR];
#pragma unroll
            for (int p = 0; p < NPAIR; p++)
                a[p] = *reinterpret_cast<const ull*>(ap + 2 * p);
            float4 bf = *reinterpret_cast<const float4*>(&Bs[kk][tx * 4]);
            ull b0 = dup2(bf.x), b1 = dup2(bf.y), b2 = dup2(bf.z), b3 = dup2(bf.w);
#pragma unroll
            for (int p = 0; p < NPAIR; p++) {
                ffma2(acc[p][0], a[p], b0, acc[p][0]);
                ffma2(acc[p][1], a[p], b1, acc[p][1]);
                ffma2(acc[p][2], a[p], b2, acc[p][2]);
                ffma2(acc[p][3], a[p], b3, acc[p][3]);
            }
        }
        __syncthreads();
    }

    // epilogue
    float bv[4];
#pragma unroll
    for (int j = 0; j < 4; j++) {
        int gc = bn + tx * 4 + j;
        bv[j] = (gc < NC) ? bias[gc] : 0.f;
    }
#pragma unroll
    for (int p = 0; p < NPAIR; p++) {
#pragma unroll
        for (int j = 0; j < 4; j++) {
            int gc = bn + tx * 4 + j;
            if (gc < NC) {
                float2 v = unpk(acc[p][j]);
                float o0 = v.x + bv[j];
                float o1 = v.y + bv[j];
                if (relu) { o0 = lrelu(o0); o1 = lrelu(o1); }
                int r0 = bm + ty * TM + 2 * p;
                if (r0 < M)     C[(size_t)r0 * ldc + col_off + gc] = o0;
                if (r0 + 1 < M) C[(size_t)(r0 + 1) * ldc + col_off + gc] = o1;
            }
        }
    }
}

// ---------------- small-K feature columns (num/cat/new -> x0 cols 53..127) ---
__global__ void feat_small_kernel(
    const float* __restrict__ numf, const float* __restrict__ catf,
    const float* __restrict__ nf,
    const float* __restrict__ Wn, const float* __restrict__ bn,
    const float* __restrict__ Wc, const float* __restrict__ bc,
    const float* __restrict__ Ww, const float* __restrict__ bw,
    float* __restrict__ x0)
{
    __shared__ float sWn[7 * 25], sbn[25], sWc[11 * 25], sbc[25], sWw[25], sbw[25];
    int tid = threadIdx.x;
    for (int i = tid; i < 7 * 25; i += blockDim.x) sWn[i] = Wn[i];
    for (int i = tid; i < 11 * 25; i += blockDim.x) sWc[i] = Wc[i];
    for (int i = tid; i < 25; i += blockDim.x) {
        sbn[i] = bn[i]; sbc[i] = bc[i]; sWw[i] = Ww[i]; sbw[i] = bw[i];
    }
    __syncthreads();

    int r = blockIdx.x * blockDim.x + tid;
    if (r >= NNODES) return;

    float nv[7], cv[11];
#pragma unroll
    for (int k = 0; k < 7; k++) nv[k] = numf[(size_t)r * 7 + k];
#pragma unroll
    for (int k = 0; k < 11; k++) cv[k] = catf[(size_t)r * 11 + k];
    float wv = nf[r];

    float* out = x0 + (size_t)r * 128;
#pragma unroll
    for (int j = 0; j < 25; j++) {
        float a = sbn[j];
#pragma unroll
        for (int k = 0; k < 7; k++) a += nv[k] * sWn[k * 25 + j];
        out[53 + j] = lrelu(a);
    }
#pragma unroll
    for (int j = 0; j < 25; j++) {
        float a = sbc[j];
#pragma unroll
        for (int k = 0; k < 11; k++) a += cv[k] * sWc[k * 25 + j];
        out[78 + j] = lrelu(a);
    }
#pragma unroll
    for (int j = 0; j < 25; j++)
        out[103 + j] = lrelu(wv * sWw[j] + sbw[j]);
}

// ---------------- CSR build ---------------------------------------------------
__global__ void zero_cnt_kernel() {
    int i = blockIdx.x * blockDim.x + threadIdx.x;
    if (i < NNODES) g_cnt[i] = 0;
}

__global__ void hist_kernel(const int* __restrict__ ei) {
    int e = blockIdx.x * blockDim.x + threadIdx.x;
    if (e < NEDGES) atomicAdd(&g_cnt[ei[NEDGES + e]], 1);
}

__global__ void scan_kernel() {
    __shared__ int wsum[32];
    __shared__ int carry;
    int tid = threadIdx.x, lane = tid & 31, wid = tid >> 5;
    if (tid == 0) carry = 0;
    __syncthreads();
    for (int base = 0; base < NNODES; base += 1024) {
        int i = base + tid;
        int v = (i < NNODES) ? g_cnt[i] : 0;
        int x = v;
#pragma unroll
        for (int o = 1; o < 32; o <<= 1) {
            int y = __shfl_up_sync(0xffffffffu, x, o);
            if (lane >= o) x += y;
        }
        if (lane == 31) wsum[wid] = x;
        __syncthreads();
        if (wid == 0) {
            int s = wsum[lane];
#pragma unroll
            for (int o = 1; o < 32; o <<= 1) {
                int y = __shfl_up_sync(0xffffffffu, s, o);
                if (lane >= o) s += y;
            }
            wsum[lane] = s;
        }
        __syncthreads();
        int c = carry;
        int woff = wid ? wsum[wid - 1] : 0;
        int excl = c + woff + x - v;
        if (i < NNODES) { g_rowptr[i] = excl; g_cursor[i] = excl; }
        int total = wsum[31];
        __syncthreads();
        if (tid == 0) carry = c + total;
        __syncthreads();
    }
    if (threadIdx.x == 0) g_rowptr[NNODES] = NEDGES;
}

__global__ void fill_kernel(const int* __restrict__ ei, const int* __restrict__ et) {
    int e = blockIdx.x * blockDim.x + threadIdx.x;
    if (e < NEDGES) {
        int s = ei[e];
        int d = ei[NEDGES + e];
        int t = et[e];
        int p = atomicAdd(&g_cursor[d], 1);
        g_adj[p] = s | (t << 30);
    }
}

// ---------------- aggregation: xa = [aggA/deg | aggB/deg | x] ----------------
__global__ void aggregate_kernel(const float* __restrict__ xin, float* __restrict__ xa) {
    int w = (blockIdx.x * blockDim.x + threadIdx.x) >> 5;
    int lane = threadIdx.x & 31;
    if (w >= NNODES) return;
    int beg = g_rowptr[w], end = g_rowptr[w + 1];
    float4 aA = make_float4(0.f, 0.f, 0.f, 0.f);
    float4 aB = make_float4(0.f, 0.f, 0.f, 0.f);
    for (int e = beg; e < end; e++) {
        int pk = g_adj[e];
        int src = pk & 0x3FFFFFFF;
        float4 v = *reinterpret_cast<const float4*>(xin + (size_t)src * 128 + lane * 4);
        if (pk >> 30) { aB.x += v.x; aB.y += v.y; aB.z += v.z; aB.w += v.w; }
        else          { aA.x += v.x; aA.y += v.y; aA.z += v.z; aA.w += v.w; }
    }
    int deg = end - beg;
    float s = 1.f / (float)(deg > 0 ? deg : 1);
    float4 xv = *reinterpret_cast<const float4*>(xin + (size_t)w * 128 + lane * 4);
    float* o = xa + (size_t)w * 384 + lane * 4;
    float4 oa = make_float4(aA.x * s, aA.y * s, aA.z * s, aA.w * s);
    float4 ob = make_float4(aB.x * s, aB.y * s, aB.z * s, aB.w * s);
    *reinterpret_cast<float4*>(o) = oa;
    *reinterpret_cast<float4*>(o + 128) = ob;
    *reinterpret_cast<float4*>(o + 256) = xv;
}

// ---------------- wcat = [rel_w0; rel_w1; root_w] (384x128) ------------------
__global__ void build_wcat_kernel(const float* __restrict__ relw,
                                  const float* __restrict__ rootw) {
    int i = blockIdx.x * blockDim.x + threadIdx.x;
    if (i < 32768) g_wcat[i] = relw[i];
    else if (i < 49152) g_wcat[i] = rootw[i - 32768];
}

// ---------------- final: out = x @ W_out2 + b_out2 (N x 2) -------------------
__global__ void final_kernel(const float* __restrict__ x,
                             const float* __restrict__ W,
                             const float* __restrict__ b,
                             float* __restrict__ out) {
    __shared__ float w[256];
    __shared__ float bb[2];
    int tid = threadIdx.x;
    for (int i = tid; i < 256; i += blockDim.x) w[i] = W[i];
    if (tid < 2) bb[tid] = b[tid];
    __syncthreads();
    int r = blockIdx.x * blockDim.x + tid;
    if (r >= NNODES) return;
    float a0 = bb[0], a1 = bb[1];
    const float4* xr = reinterpret_cast<const float4*>(x + (size_t)r * 128);
#pragma unroll
    for (int k4 = 0; k4 < 32; k4++) {
        float4 v = xr[k4];
        int k = k4 * 4;
        a0 += v.x * w[2 * k + 0]; a1 += v.x * w[2 * k + 1];
        a0 += v.y * w[2 * k + 2]; a1 += v.y * w[2 * k + 3];
        a0 += v.z * w[2 * k + 4]; a1 += v.z * w[2 * k + 5];
        a0 += v.w * w[2 * k + 6]; a1 += v.w * w[2 * k + 7];
    }
    out[(size_t)r * 2 + 0] = a0;
    out[(size_t)r * 2 + 1] = a1;
}

// ---------------- launch ------------------------------------------------------
extern "C" void kernel_launch(void* const* d_in, const int* in_sizes, int n_in,
                              void* d_out, int out_size)
{
    // Input ordering: either setup_inputs() dict order (edge_index at idx 5)
    // or reference() signature order (edge_index at idx 27). Disambiguate by size.
    const bool setup_order = (in_sizes[5] == 2 * NEDGES);

    const float* des   = (const float*)d_in[0];
    const float* tweet = (const float*)d_in[1];
    const float* numf  = (const float*)d_in[2];
    const float* catf  = (const float*)d_in[3];
    const float* nf    = (const float*)d_in[4];
    const int* ei;
    const int* et;
    int wbase;
    if (setup_order) { ei = (const int*)d_in[5]; et = (const int*)d_in[6]; wbase = 7; }
    else             { ei = (const int*)d_in[27]; et = (const int*)d_in[28]; wbase = 5; }

#define WI(k) ((const float*)d_in[wbase + (k)])
    const float* W_des   = WI(0);  const float* b_des   = WI(1);
    const float* W_tweet = WI(2);  const float* b_tweet = WI(3);
    const float* W_num   = WI(4);  const float* b_num   = WI(5);
    const float* W_cat   = WI(6);  const float* b_cat   = WI(7);
    const float* W_new   = WI(8);  const float* b_new   = WI(9);
    const float* W_in    = WI(10); const float* b_in    = WI(11);
    const float* rel_w1  = WI(12); const float* root_w1 = WI(13); const float* bias1 = WI(14);
    const float* rel_w2  = WI(15); const float* root_w2 = WI(16); const float* bias2 = WI(17);
    const float* W_out1  = WI(18); const float* b_out1  = WI(19);
    const float* W_out2  = WI(20); const float* b_out2  = WI(21);
#undef WI

    float *x0, *x1, *x2, *x3, *xa, *wcat;
    cudaGetSymbolAddress((void**)&x0, g_x0);
    cudaGetSymbolAddress((void**)&x1, g_x1);
    cudaGetSymbolAddress((void**)&x2, g_x2);
    cudaGetSymbolAddress((void**)&x3, g_x3);
    cudaGetSymbolAddress((void**)&xa, g_xa);
    cudaGetSymbolAddress((void**)&wcat, g_wcat);

    const int MB = (NNODES + 127) / 128;  // 391

    // Feature transforms -> x0 [N,128]
    feat_small_kernel<<<(NNODES + 255) / 256, 256>>>(
        numf, catf, nf, W_num, b_num, W_cat, b_cat, W_new, b_new, x0);
    gemm_kernel<32><<<dim3(MB, 1), 256>>>(des, 768, W_des, 25, b_des,
                                          x0, 128, 0, NNODES, 768, 25, 1);
    gemm_kernel<32><<<dim3(MB, 1), 256>>>(tweet, 768, W_tweet, 28, b_tweet,
                                          x0, 128, 25, NNODES, 768, 28, 1);
    // x1 = lrelu(x0 @ W_in + b_in)
    gemm_kernel<64><<<dim3(MB, 2), 256>>>(x0, 128, W_in, 128, b_in,
                                          x1, 128, 0, NNODES, 128, 128, 1);

    // CSR by destination (shared by both RGCN layers)
    zero_cnt_kernel<<<(NNODES + 255) / 256, 256>>>();
    hist_kernel<<<(NEDGES + 255) / 256, 256>>>(ei);
    scan_kernel<<<1, 1024>>>();
    fill_kernel<<<(NEDGES + 255) / 256, 256>>>(ei, et);

    const int AGG_BLOCKS = (NNODES * 32 + 255) / 256;

    // RGCN layer 1: x2 = [aggA/deg | aggB/deg | x1] @ [relW1_0; relW1_1; rootW1] + bias1
    build_wcat_kernel<<<192, 256>>>(rel_w1, root_w1);
    aggregate_kernel<<<AGG_BLOCKS, 256>>>(x1, xa);
    gemm_kernel<64><<<dim3(MB, 2), 256>>>(xa, 384, wcat, 128, bias1,
                                          x2, 128, 0, NNODES, 384, 128, 0);

    // RGCN layer 2
    build_wcat_kernel<<<192, 256>>>(rel_w2, root_w2);
    aggregate_kernel<<<AGG_BLOCKS, 256>>>(x2, xa);
    gemm_kernel<64><<<dim3(MB, 2), 256>>>(xa, 384, wcat, 128, bias2,
                                          x3, 128, 0, NNODES, 384, 128, 0);

    // Head: x1 = lrelu(x3 @ W_out1 + b_out1); out = x1 @ W_out2 + b_out2
    gemm_kernel<64><<<dim3(MB, 2), 256>>>(x3, 128, W_out1, 128, b_out1,
                                          x1, 128, 0, NNODES, 128, 128, 1);
    final_kernel<<<(NNODES + 255) / 256, 256>>>(x1, W_out2, b_out2, (float*)d_out);
}